// round 1
// baseline (speedup 1.0000x reference)
#include <cuda_runtime.h>
#include <cstdint>

#define Bsz 512
#define Tsz 256
#define Dsz 128
#define Hsz 512
#define GIN 768
#define TB  (Tsz*Bsz)          /* 131072 */
#define BH  (Bsz*Hsz)          /* 262144 */

static const size_t TBH = (size_t)TB * Hsz;   /* 67108864 */

// ---------------- scratch (__device__ globals: allocation-free) ----------------
__device__ float g_xm[50331648];     // (T*B, 384) = [x_tilde | mask | delta]
__device__ float g_A [201326592];    // 3 x (T*B, H): pre-activation affine terms z,r,n
__device__ float g_gh[67108864];     // (T*B, H): hidden decay gamma_h
__device__ float g_h [2][BH];        // double-buffered hidden state
__device__ float g_Z [BH];           // z gate
__device__ float g_RH[BH];           // r * hd

// ---------------- f32x2 helpers (FFMA2: 2x fp32 MAC throughput on sm_103a) ----
typedef unsigned long long ull;
__device__ __forceinline__ ull pk2(float lo, float hi) {
    ull r; asm("mov.b64 %0,{%1,%2};" : "=l"(r) : "f"(lo), "f"(hi)); return r;
}
__device__ __forceinline__ void fma2(ull &c, ull a, ull b) {
    asm("fma.rn.f32x2 %0,%1,%2,%0;" : "+l"(c) : "l"(a), "l"(b));
}
__device__ __forceinline__ void upk(ull v, float &lo, float &hi) {
    asm("mov.b64 {%0,%1},%2;" : "=f"(lo), "=f"(hi) : "l"(v));
}
__device__ __forceinline__ float sigm(float x) { return 1.f / (1.f + expf(-x)); }

// ---------------- P0: elementwise input-decay / staging ----------------
// builds g_xm[(t*B+b)*384 + {d, 128+d, 256+d}] = {x_tilde, m, delta}
__global__ void p0_kernel(const float* __restrict__ x,  const float* __restrict__ xl,
                          const float* __restrict__ mk, const float* __restrict__ dl,
                          const float* __restrict__ xmean,
                          const float* __restrict__ Wgx, const float* __restrict__ bgx) {
    int idx = blockIdx.x * 256 + threadIdx.x;      // (t*B+b)*D + d
    int d   = idx & 127;
    int row = idx >> 7;                            // t*B + b
    int t   = row >> 9;
    int b   = row & 511;
    size_t xi = ((size_t)b * Tsz + t) * Dsz + d;   // inputs are (B,T,D)
    float dv = dl[xi], mv = mk[xi];
    float gx = expf(-fmaxf(0.f, dv * Wgx[d * Dsz + d] + bgx[d]));
    float xt = mv * x[xi] + (1.f - mv) * (gx * xl[xi] + (1.f - gx) * xmean[d]);
    size_t o = (size_t)row * 384;
    g_xm[o + d]       = xt;
    g_xm[o + 128 + d] = mv;
    g_xm[o + 256 + d] = dv;
}

// ---------------- P1: A_s = [xt|m] @ W_s[:, {0:128,640:768}].T + b_s ----------
// GEMM M=131072, N=512, K=256.  128x128 tile, 256 thr, 8x8 micro, FFMA2.
__global__ __launch_bounds__(256) void p1_kernel(
        const float* __restrict__ Wz, const float* __restrict__ bz,
        const float* __restrict__ Wr, const float* __restrict__ br,
        const float* __restrict__ Wn, const float* __restrict__ bn) {
    int s = blockIdx.z;
    const float* W    = (s == 0) ? Wz : (s == 1) ? Wr : Wn;
    const float* bias = (s == 0) ? bz : (s == 1) ? br : bn;
    float* out = g_A + (size_t)s * TBH;
    int r0 = blockIdx.x * 128, j0 = blockIdx.y * 128;
    __shared__ float As[16][132];
    __shared__ float Bs[16][132];
    int tid = threadIdx.x, tx = tid & 15, ty = tid >> 4;
    ull acc[8][4];
    #pragma unroll
    for (int i = 0; i < 8; i++)
        #pragma unroll
        for (int j = 0; j < 4; j++) acc[i][j] = 0ull;

    for (int k0 = 0; k0 < 256; k0 += 16) {
        #pragma unroll
        for (int u = 0; u < 8; u++) {
            int e = tid + u * 256;
            int k = e & 15, row = e >> 4;
            As[k][row] = g_xm[(size_t)(r0 + row) * 384 + (k0 + k)];
            int kq  = k0 + k;
            int col = (kq < 128) ? kq : kq + 512;  // x-cols 0:128, m-cols 640:768
            Bs[k][row] = W[(size_t)(j0 + row) * GIN + col];
        }
        __syncthreads();
        #pragma unroll
        for (int kk = 0; kk < 16; kk++) {
            float4 a0 = *(const float4*)&As[kk][ty * 8];
            float4 a1 = *(const float4*)&As[kk][ty * 8 + 4];
            float4 b0 = *(const float4*)&Bs[kk][tx * 8];
            float4 b1 = *(const float4*)&Bs[kk][tx * 8 + 4];
            ull bb[4] = { pk2(b0.x,b0.y), pk2(b0.z,b0.w), pk2(b1.x,b1.y), pk2(b1.z,b1.w) };
            ull aa[8] = { pk2(a0.x,a0.x), pk2(a0.y,a0.y), pk2(a0.z,a0.z), pk2(a0.w,a0.w),
                          pk2(a1.x,a1.x), pk2(a1.y,a1.y), pk2(a1.z,a1.z), pk2(a1.w,a1.w) };
            #pragma unroll
            for (int i = 0; i < 8; i++)
                #pragma unroll
                for (int j = 0; j < 4; j++) fma2(acc[i][j], aa[i], bb[j]);
        }
        __syncthreads();
    }
    #pragma unroll
    for (int i = 0; i < 8; i++) {
        size_t r = (size_t)(r0 + ty * 8 + i);
        #pragma unroll
        for (int j4 = 0; j4 < 4; j4++) {
            float lo, hi; upk(acc[i][j4], lo, hi);
            int j = j0 + tx * 8 + j4 * 2;
            out[r * Hsz + j]     = lo + bias[j];
            out[r * Hsz + j + 1] = hi + bias[j + 1];
        }
    }
}

// ---------------- P2: gh = exp(-relu(delta @ Wgh.T + bgh)) --------------------
// GEMM M=131072, N=512, K=128, same tiling as P1.
__global__ __launch_bounds__(256) void p2_kernel(const float* __restrict__ Wgh,
                                                 const float* __restrict__ bgh) {
    int r0 = blockIdx.x * 128, j0 = blockIdx.y * 128;
    __shared__ float As[16][132];
    __shared__ float Bs[16][132];
    int tid = threadIdx.x, tx = tid & 15, ty = tid >> 4;
    ull acc[8][4];
    #pragma unroll
    for (int i = 0; i < 8; i++)
        #pragma unroll
        for (int j = 0; j < 4; j++) acc[i][j] = 0ull;

    for (int k0 = 0; k0 < 128; k0 += 16) {
        #pragma unroll
        for (int u = 0; u < 8; u++) {
            int e = tid + u * 256;
            int k = e & 15, row = e >> 4;
            As[k][row] = g_xm[(size_t)(r0 + row) * 384 + 256 + (k0 + k)];
            Bs[k][row] = Wgh[(size_t)(j0 + row) * Dsz + (k0 + k)];
        }
        __syncthreads();
        #pragma unroll
        for (int kk = 0; kk < 16; kk++) {
            float4 a0 = *(const float4*)&As[kk][ty * 8];
            float4 a1 = *(const float4*)&As[kk][ty * 8 + 4];
            float4 b0 = *(const float4*)&Bs[kk][tx * 8];
            float4 b1 = *(const float4*)&Bs[kk][tx * 8 + 4];
            ull bb[4] = { pk2(b0.x,b0.y), pk2(b0.z,b0.w), pk2(b1.x,b1.y), pk2(b1.z,b1.w) };
            ull aa[8] = { pk2(a0.x,a0.x), pk2(a0.y,a0.y), pk2(a0.z,a0.z), pk2(a0.w,a0.w),
                          pk2(a1.x,a1.x), pk2(a1.y,a1.y), pk2(a1.z,a1.z), pk2(a1.w,a1.w) };
            #pragma unroll
            for (int i = 0; i < 8; i++)
                #pragma unroll
                for (int j = 0; j < 4; j++) fma2(acc[i][j], aa[i], bb[j]);
        }
        __syncthreads();
    }
    #pragma unroll
    for (int i = 0; i < 8; i++) {
        size_t r = (size_t)(r0 + ty * 8 + i);
        #pragma unroll
        for (int j4 = 0; j4 < 4; j4++) {
            float lo, hi; upk(acc[i][j4], lo, hi);
            int j = j0 + tx * 8 + j4 * 2;
            g_gh[r * Hsz + j]     = expf(-fmaxf(0.f, lo + bgh[j]));
            g_gh[r * Hsz + j + 1] = expf(-fmaxf(0.f, hi + bgh[j + 1]));
        }
    }
}

// ---------------- K1: z and r GEMMs (per step) --------------------------------
// hd = gh .* h_prev ;  z = sigm(A_z + hd@Uz.T) ; rh = sigm(A_r + hd@Ur.T).*hd
// 64x64 tile, 128 thr, 4x8 micro. grid (8 rowtiles, 8 coltiles, 2 mats) = 128 CTAs
__global__ __launch_bounds__(128) void k1_kernel(int t, const float* __restrict__ Wz,
                                                        const float* __restrict__ Wr) {
    int s = blockIdx.z;
    const float* W  = s ? Wr : Wz;
    int b0 = blockIdx.x * 64, j0 = blockIdx.y * 64;
    const float* hp = g_h[t & 1];
    const float* gh = g_gh + (size_t)t * BH;
    __shared__ float As[16][68];
    __shared__ float Bs[16][68];
    int tid = threadIdx.x, tx = tid & 7, ty = tid >> 3;
    ull acc[4][4];
    #pragma unroll
    for (int i = 0; i < 4; i++)
        #pragma unroll
        for (int j = 0; j < 4; j++) acc[i][j] = 0ull;

    for (int k0 = 0; k0 < Hsz; k0 += 16) {
        #pragma unroll
        for (int u = 0; u < 8; u++) {
            int e = tid + u * 128;
            int k = e & 15, row = e >> 4;
            size_t gi = (size_t)(b0 + row) * Hsz + (k0 + k);
            As[k][row] = gh[gi] * hp[gi];
            Bs[k][row] = W[(size_t)(j0 + row) * GIN + 128 + (k0 + k)];
        }
        __syncthreads();
        #pragma unroll
        for (int kk = 0; kk < 16; kk++) {
            float4 a  = *(const float4*)&As[kk][ty * 4];
            float4 v0 = *(const float4*)&Bs[kk][tx * 8];
            float4 v1 = *(const float4*)&Bs[kk][tx * 8 + 4];
            ull bb[4] = { pk2(v0.x,v0.y), pk2(v0.z,v0.w), pk2(v1.x,v1.y), pk2(v1.z,v1.w) };
            ull aa[4] = { pk2(a.x,a.x), pk2(a.y,a.y), pk2(a.z,a.z), pk2(a.w,a.w) };
            #pragma unroll
            for (int i = 0; i < 4; i++)
                #pragma unroll
                for (int j = 0; j < 4; j++) fma2(acc[i][j], aa[i], bb[j]);
        }
        __syncthreads();
    }
    const float* Aterm = g_A + (size_t)s * TBH + (size_t)t * BH;
    #pragma unroll
    for (int i = 0; i < 4; i++) {
        int b = b0 + ty * 4 + i;
        #pragma unroll
        for (int j4 = 0; j4 < 4; j4++) {
            float lo, hi; upk(acc[i][j4], lo, hi);
            int j = j0 + tx * 8 + j4 * 2;
            size_t o = (size_t)b * Hsz + j;
            float v0 = sigm(lo + Aterm[o]);
            float v1 = sigm(hi + Aterm[o + 1]);
            if (s == 0) {
                g_Z[o]     = v0;
                g_Z[o + 1] = v1;
            } else {
                g_RH[o]     = v0 * gh[o]     * hp[o];
                g_RH[o + 1] = v1 * gh[o + 1] * hp[o + 1];
            }
        }
    }
}

// ---------------- K2: h_tilde GEMM + state update (per step) ------------------
// h_tilde = tanh(A_n + (r.*hd)@Un.T);  h_next = (1-z).*hd + z.*h_tilde
// 32x64 tile, 128 thr, 2x8 micro. grid (16,8) = 128 CTAs
__global__ __launch_bounds__(128) void k2_kernel(int t, const float* __restrict__ Wn) {
    int b0 = blockIdx.x * 32, j0 = blockIdx.y * 64;
    const float* hp = g_h[t & 1];
    float*       hn = g_h[(t + 1) & 1];
    const float* gh = g_gh + (size_t)t * BH;
    __shared__ float As[16][36];
    __shared__ float Bs[16][68];
    int tid = threadIdx.x, tx = tid & 7, ty = tid >> 3;
    ull acc[2][4];
    #pragma unroll
    for (int i = 0; i < 2; i++)
        #pragma unroll
        for (int j = 0; j < 4; j++) acc[i][j] = 0ull;

    for (int k0 = 0; k0 < Hsz; k0 += 16) {
        #pragma unroll
        for (int u = 0; u < 4; u++) {
            int e = tid + u * 128;
            int k = e & 15, row = e >> 4;
            As[k][row] = g_RH[(size_t)(b0 + row) * Hsz + (k0 + k)];
        }
        #pragma unroll
        for (int u = 0; u < 8; u++) {
            int e = tid + u * 128;
            int k = e & 15, row = e >> 4;
            Bs[k][row] = Wn[(size_t)(j0 + row) * GIN + 128 + (k0 + k)];
        }
        __syncthreads();
        #pragma unroll
        for (int kk = 0; kk < 16; kk++) {
            float2 a  = *(const float2*)&As[kk][ty * 2];
            float4 v0 = *(const float4*)&Bs[kk][tx * 8];
            float4 v1 = *(const float4*)&Bs[kk][tx * 8 + 4];
            ull bb[4] = { pk2(v0.x,v0.y), pk2(v0.z,v0.w), pk2(v1.x,v1.y), pk2(v1.z,v1.w) };
            ull aa[2] = { pk2(a.x,a.x), pk2(a.y,a.y) };
            #pragma unroll
            for (int i = 0; i < 2; i++)
                #pragma unroll
                for (int j = 0; j < 4; j++) fma2(acc[i][j], aa[i], bb[j]);
        }
        __syncthreads();
    }
    const float* An = g_A + 2 * TBH + (size_t)t * BH;
    #pragma unroll
    for (int i = 0; i < 2; i++) {
        int b = b0 + ty * 2 + i;
        #pragma unroll
        for (int j4 = 0; j4 < 4; j4++) {
            float lo, hi; upk(acc[i][j4], lo, hi);
            int j = j0 + tx * 8 + j4 * 2;
            size_t o = (size_t)b * Hsz + j;
            float ht0 = tanhf(lo + An[o]);
            float ht1 = tanhf(hi + An[o + 1]);
            float z0  = g_Z[o],       z1  = g_Z[o + 1];
            float hv0 = gh[o] * hp[o], hv1 = gh[o + 1] * hp[o + 1];
            hn[o]     = (1.f - z0) * hv0 + z0 * ht0;
            hn[o + 1] = (1.f - z1) * hv1 + z1 * ht1;
        }
    }
}

// ---------------- init / final ----------------
__global__ void zero_h0_kernel() {
    int i = blockIdx.x * 256 + threadIdx.x;
    g_h[0][i] = 0.f;
}
__global__ void copy_out_kernel(float* __restrict__ out) {
    int i = blockIdx.x * 256 + threadIdx.x;
    out[i] = g_h[0][i];   // T=256 even -> final state lands in buffer 0
}

// ---------------- launch ----------------
extern "C" void kernel_launch(void* const* d_in, const int* in_sizes, int n_in,
                              void* d_out, int out_size) {
    const float* x    = (const float*)d_in[0];
    const float* xl   = (const float*)d_in[1];
    const float* mk   = (const float*)d_in[2];
    const float* dl   = (const float*)d_in[3];
    const float* xm   = (const float*)d_in[4];
    const float* Wz   = (const float*)d_in[5];
    const float* bz   = (const float*)d_in[6];
    const float* Wr   = (const float*)d_in[7];
    const float* br   = (const float*)d_in[8];
    const float* Wn   = (const float*)d_in[9];
    const float* bn   = (const float*)d_in[10];
    const float* Wgx  = (const float*)d_in[11];
    const float* bgx  = (const float*)d_in[12];
    const float* Wgh  = (const float*)d_in[13];
    const float* bgh  = (const float*)d_in[14];

    p0_kernel<<<(TB * Dsz) / 256, 256>>>(x, xl, mk, dl, xm, Wgx, bgx);
    p1_kernel<<<dim3(TB / 128, Hsz / 128, 3), 256>>>(Wz, bz, Wr, br, Wn, bn);
    p2_kernel<<<dim3(TB / 128, Hsz / 128), 256>>>(Wgh, bgh);
    zero_h0_kernel<<<BH / 256, 256>>>();

    for (int t = 0; t < Tsz; t++) {
        k1_kernel<<<dim3(8, 8, 2), 128>>>(t, Wz, Wr);
        k2_kernel<<<dim3(16, 8), 128>>>(t, Wn);
    }
    copy_out_kernel<<<BH / 256, 256>>>((float*)d_out);
}

// round 2
// speedup vs baseline: 1.6295x; 1.6295x over previous
#include <cuda_runtime.h>
#include <cstdint>

#define Bsz 512
#define Tsz 256
#define Dsz 128
#define Hsz 512
#define GIN 768
#define TB  (Tsz*Bsz)          /* 131072 */
#define BH  (Bsz*Hsz)          /* 262144 */
#define NCTA 128

static const size_t TBH = (size_t)TB * Hsz;   /* 67108864 */

// ---------------- scratch (__device__ globals: allocation-free) ----------------
__device__ float g_xm[50331648];     // (T*B, 384) = [x_tilde | mask | delta]
__device__ float g_A [201326592];    // 3 x (T*B, H): affine terms z,r,n
__device__ float g_gh[67108864];     // (T*B, H): hidden decay gamma_h
__device__ float g_hbuf[BH];         // hidden state (single buffer)
__device__ float g_Z [BH];           // z gate
__device__ float g_RH[BH];           // r * hd
__device__ unsigned g_barrier;       // grid barrier arrival counter

// ---------------- f32x2 helpers ----------------
typedef unsigned long long ull;
__device__ __forceinline__ ull pk2(float lo, float hi) {
    ull r; asm("mov.b64 %0,{%1,%2};" : "=l"(r) : "f"(lo), "f"(hi)); return r;
}
__device__ __forceinline__ void fma2(ull &c, ull a, ull b) {
    asm("fma.rn.f32x2 %0,%1,%2,%0;" : "+l"(c) : "l"(a), "l"(b));
}
__device__ __forceinline__ void upk(ull v, float &lo, float &hi) {
    asm("mov.b64 {%0,%1},%2;" : "=f"(lo), "=f"(hi) : "l"(v));
}
__device__ __forceinline__ float sigm(float x) { return 1.f / (1.f + expf(-x)); }

// ---------------- grid barrier ----------------
__device__ __forceinline__ void gsync(unsigned &target) {
    __syncthreads();
    __threadfence();
    if (threadIdx.x == 0) {
        atomicAdd(&g_barrier, 1u);
        while (*((volatile unsigned*)&g_barrier) < target) { }
    }
    __syncthreads();
    target += NCTA;
}

__global__ void zero_bar_kernel() { g_barrier = 0u; }

// ---------------- P0: elementwise input-decay / staging ----------------
__global__ void p0_kernel(const float* __restrict__ x,  const float* __restrict__ xl,
                          const float* __restrict__ mk, const float* __restrict__ dl,
                          const float* __restrict__ xmean,
                          const float* __restrict__ Wgx, const float* __restrict__ bgx) {
    int idx = blockIdx.x * 256 + threadIdx.x;
    int d   = idx & 127;
    int row = idx >> 7;
    int t   = row >> 9;
    int b   = row & 511;
    size_t xi = ((size_t)b * Tsz + t) * Dsz + d;
    float dv = dl[xi], mv = mk[xi];
    float gx = expf(-fmaxf(0.f, dv * Wgx[d * Dsz + d] + bgx[d]));
    float xt = mv * x[xi] + (1.f - mv) * (gx * xl[xi] + (1.f - gx) * xmean[d]);
    size_t o = (size_t)row * 384;
    g_xm[o + d]       = xt;
    g_xm[o + 128 + d] = mv;
    g_xm[o + 256 + d] = dv;
}

// ---------------- P1: A_s = [xt|m] @ W_s[:, {0:128,640:768}].T + b_s ----------
__global__ __launch_bounds__(256) void p1_kernel(
        const float* __restrict__ Wz, const float* __restrict__ bz,
        const float* __restrict__ Wr, const float* __restrict__ br,
        const float* __restrict__ Wn, const float* __restrict__ bn) {
    int s = blockIdx.z;
    const float* W    = (s == 0) ? Wz : (s == 1) ? Wr : Wn;
    const float* bias = (s == 0) ? bz : (s == 1) ? br : bn;
    float* out = g_A + (size_t)s * TBH;
    int r0 = blockIdx.x * 128, j0 = blockIdx.y * 128;
    __shared__ float As[16][132];
    __shared__ float Bs[16][132];
    int tid = threadIdx.x, tx = tid & 15, ty = tid >> 4;
    ull acc[8][4];
    #pragma unroll
    for (int i = 0; i < 8; i++)
        #pragma unroll
        for (int j = 0; j < 4; j++) acc[i][j] = 0ull;

    for (int k0 = 0; k0 < 256; k0 += 16) {
        #pragma unroll
        for (int u = 0; u < 8; u++) {
            int e = tid + u * 256;
            int k = e & 15, row = e >> 4;
            As[k][row] = g_xm[(size_t)(r0 + row) * 384 + (k0 + k)];
            int kq  = k0 + k;
            int col = (kq < 128) ? kq : kq + 512;
            Bs[k][row] = W[(size_t)(j0 + row) * GIN + col];
        }
        __syncthreads();
        #pragma unroll
        for (int kk = 0; kk < 16; kk++) {
            float4 a0 = *(const float4*)&As[kk][ty * 8];
            float4 a1 = *(const float4*)&As[kk][ty * 8 + 4];
            float4 b0 = *(const float4*)&Bs[kk][tx * 8];
            float4 b1 = *(const float4*)&Bs[kk][tx * 8 + 4];
            ull bb[4] = { pk2(b0.x,b0.y), pk2(b0.z,b0.w), pk2(b1.x,b1.y), pk2(b1.z,b1.w) };
            ull aa[8] = { pk2(a0.x,a0.x), pk2(a0.y,a0.y), pk2(a0.z,a0.z), pk2(a0.w,a0.w),
                          pk2(a1.x,a1.x), pk2(a1.y,a1.y), pk2(a1.z,a1.z), pk2(a1.w,a1.w) };
            #pragma unroll
            for (int i = 0; i < 8; i++)
                #pragma unroll
                for (int j = 0; j < 4; j++) fma2(acc[i][j], aa[i], bb[j]);
        }
        __syncthreads();
    }
    #pragma unroll
    for (int i = 0; i < 8; i++) {
        size_t r = (size_t)(r0 + ty * 8 + i);
        #pragma unroll
        for (int j4 = 0; j4 < 4; j4++) {
            float lo, hi; upk(acc[i][j4], lo, hi);
            int j = j0 + tx * 8 + j4 * 2;
            out[r * Hsz + j]     = lo + bias[j];
            out[r * Hsz + j + 1] = hi + bias[j + 1];
        }
    }
}

// ---------------- P2: gh = exp(-relu(delta @ Wgh.T + bgh)) --------------------
__global__ __launch_bounds__(256) void p2_kernel(const float* __restrict__ Wgh,
                                                 const float* __restrict__ bgh) {
    int r0 = blockIdx.x * 128, j0 = blockIdx.y * 128;
    __shared__ float As[16][132];
    __shared__ float Bs[16][132];
    int tid = threadIdx.x, tx = tid & 15, ty = tid >> 4;
    ull acc[8][4];
    #pragma unroll
    for (int i = 0; i < 8; i++)
        #pragma unroll
        for (int j = 0; j < 4; j++) acc[i][j] = 0ull;

    for (int k0 = 0; k0 < 128; k0 += 16) {
        #pragma unroll
        for (int u = 0; u < 8; u++) {
            int e = tid + u * 256;
            int k = e & 15, row = e >> 4;
            As[k][row] = g_xm[(size_t)(r0 + row) * 384 + 256 + (k0 + k)];
            Bs[k][row] = Wgh[(size_t)(j0 + row) * Dsz + (k0 + k)];
        }
        __syncthreads();
        #pragma unroll
        for (int kk = 0; kk < 16; kk++) {
            float4 a0 = *(const float4*)&As[kk][ty * 8];
            float4 a1 = *(const float4*)&As[kk][ty * 8 + 4];
            float4 b0 = *(const float4*)&Bs[kk][tx * 8];
            float4 b1 = *(const float4*)&Bs[kk][tx * 8 + 4];
            ull bb[4] = { pk2(b0.x,b0.y), pk2(b0.z,b0.w), pk2(b1.x,b1.y), pk2(b1.z,b1.w) };
            ull aa[8] = { pk2(a0.x,a0.x), pk2(a0.y,a0.y), pk2(a0.z,a0.z), pk2(a0.w,a0.w),
                          pk2(a1.x,a1.x), pk2(a1.y,a1.y), pk2(a1.z,a1.z), pk2(a1.w,a1.w) };
            #pragma unroll
            for (int i = 0; i < 8; i++)
                #pragma unroll
                for (int j = 0; j < 4; j++) fma2(acc[i][j], aa[i], bb[j]);
        }
        __syncthreads();
    }
    #pragma unroll
    for (int i = 0; i < 8; i++) {
        size_t r = (size_t)(r0 + ty * 8 + i);
        #pragma unroll
        for (int j4 = 0; j4 < 4; j4++) {
            float lo, hi; upk(acc[i][j4], lo, hi);
            int j = j0 + tx * 8 + j4 * 2;
            g_gh[r * Hsz + j]     = expf(-fmaxf(0.f, lo + bgh[j]));
            g_gh[r * Hsz + j + 1] = expf(-fmaxf(0.f, hi + bgh[j + 1]));
        }
    }
}

// ---------------- persistent recurrent loop kernel ----------------------------
// 128 CTAs x 256 threads, all co-resident (1 CTA/SM via smem).
// Per CTA persistent smem:
//   WAf[512][64] : this CTA's phase-A weight slice (Uz or Ur), k-major
//   WBf[512][32] : this CTA's phase-B weight slice (Un), k-major
//   Asf[32][68]  : per-chunk activation staging (transposed)
__global__ __launch_bounds__(256, 1) void loop_kernel(
        const float* __restrict__ Wz, const float* __restrict__ Wr,
        const float* __restrict__ Wn, float* __restrict__ out) {
    extern __shared__ float sm[];
    float* WAf = sm;                    // 32768 floats
    float* WBf = sm + 32768;            // 16384 floats
    float* Asf = sm + 32768 + 16384;    // 32*68 = 2176 floats

    int cta = blockIdx.x, tid = threadIdx.x;
    int sA  = cta >> 6;                        // 0 = z gate, 1 = r gate
    int jA0 = ((cta >> 3) & 7) * 64, bA0 = (cta & 7) * 64;
    int jB0 = (cta & 15) * 32,       bB0 = (cta >> 4) * 64;
    const float* WsA = sA ? Wr : Wz;

    // one-time: load persistent weight slices into smem (k-major)
    for (int i = tid; i < 512 * 64; i += 256) {
        int j = i >> 9, k = i & 511;
        WAf[k * 64 + j] = WsA[(size_t)(jA0 + j) * GIN + 128 + k];
    }
    for (int i = tid; i < 512 * 32; i += 256) {
        int j = i >> 9, k = i & 511;
        WBf[k * 32 + j] = Wn[(size_t)(jB0 + j) * GIN + 128 + k];
    }
    // zero h
    for (int i = tid; i < 2048; i += 256) g_hbuf[cta * 2048 + i] = 0.f;

    unsigned target = NCTA;
    gsync(target);

    for (int t = 0; t < Tsz; t++) {
        const float* gh = g_gh + (size_t)t * BH;

        // ================= phase A: z (sA=0) or r*hd (sA=1) ===================
        {
            int tx = tid & 15, ty = tid >> 4;      // j micro 4, b micro 4
            ull acc[4][2];
            #pragma unroll
            for (int i = 0; i < 4; i++) { acc[i][0] = 0ull; acc[i][1] = 0ull; }

            float4 pg[2], ph[2];
            // prefetch chunk 0
            #pragma unroll
            for (int q = 0; q < 2; q++) {
                int f = tid + q * 256; int row = f >> 3, kp = (f & 7) * 4;
                size_t gi = (size_t)(bA0 + row) * Hsz + kp;
                pg[q] = *(const float4*)(gh + gi);
                ph[q] = __ldcg((const float4*)(g_hbuf + gi));
            }
            for (int c = 0; c < 16; c++) {
                __syncthreads();
                #pragma unroll
                for (int q = 0; q < 2; q++) {
                    int f = tid + q * 256; int row = f >> 3, kp = (f & 7) * 4;
                    Asf[(kp + 0) * 68 + row] = pg[q].x * ph[q].x;
                    Asf[(kp + 1) * 68 + row] = pg[q].y * ph[q].y;
                    Asf[(kp + 2) * 68 + row] = pg[q].z * ph[q].z;
                    Asf[(kp + 3) * 68 + row] = pg[q].w * ph[q].w;
                }
                __syncthreads();
                if (c < 15) {
                    #pragma unroll
                    for (int q = 0; q < 2; q++) {
                        int f = tid + q * 256; int row = f >> 3, kp = (f & 7) * 4;
                        size_t gi = (size_t)(bA0 + row) * Hsz + (c + 1) * 32 + kp;
                        pg[q] = *(const float4*)(gh + gi);
                        ph[q] = __ldcg((const float4*)(g_hbuf + gi));
                    }
                }
                const float* wbase = WAf + c * 32 * 64;
                #pragma unroll
                for (int kk = 0; kk < 32; kk++) {
                    float4 a = *(const float4*)(Asf + kk * 68 + ty * 4);
                    float4 b = *(const float4*)(wbase + kk * 64 + tx * 4);
                    ull bb0 = pk2(b.x, b.y), bb1 = pk2(b.z, b.w);
                    ull a0 = pk2(a.x, a.x), a1 = pk2(a.y, a.y);
                    ull a2 = pk2(a.z, a.z), a3 = pk2(a.w, a.w);
                    fma2(acc[0][0], a0, bb0); fma2(acc[0][1], a0, bb1);
                    fma2(acc[1][0], a1, bb0); fma2(acc[1][1], a1, bb1);
                    fma2(acc[2][0], a2, bb0); fma2(acc[2][1], a2, bb1);
                    fma2(acc[3][0], a3, bb0); fma2(acc[3][1], a3, bb1);
                }
            }
            // epilogue
            const float* At = g_A + (size_t)sA * TBH + (size_t)t * BH;
            #pragma unroll
            for (int i = 0; i < 4; i++) {
                int b = bA0 + ty * 4 + i;
                #pragma unroll
                for (int p = 0; p < 2; p++) {
                    float lo, hi; upk(acc[i][p], lo, hi);
                    int j = jA0 + tx * 4 + p * 2;
                    size_t o = (size_t)b * Hsz + j;
                    float v0 = sigm(lo + At[o]);
                    float v1 = sigm(hi + At[o + 1]);
                    if (sA == 0) {
                        g_Z[o]     = v0;
                        g_Z[o + 1] = v1;
                    } else {
                        float hd0 = gh[o]     * __ldcg(g_hbuf + o);
                        float hd1 = gh[o + 1] * __ldcg(g_hbuf + o + 1);
                        g_RH[o]     = v0 * hd0;
                        g_RH[o + 1] = v1 * hd1;
                    }
                }
            }
        }
        gsync(target);

        // ================= phase B: h_tilde + state update ====================
        {
            int tx = tid & 7, ty = tid >> 3;       // j micro 4, b micro 2
            ull acc[2][2];
            acc[0][0] = acc[0][1] = acc[1][0] = acc[1][1] = 0ull;

            float4 pr[2];
            #pragma unroll
            for (int q = 0; q < 2; q++) {
                int f = tid + q * 256; int row = f >> 3, kp = (f & 7) * 4;
                pr[q] = __ldcg((const float4*)(g_RH + (size_t)(bB0 + row) * Hsz + kp));
            }
            for (int c = 0; c < 16; c++) {
                __syncthreads();
                #pragma unroll
                for (int q = 0; q < 2; q++) {
                    int f = tid + q * 256; int row = f >> 3, kp = (f & 7) * 4;
                    Asf[(kp + 0) * 68 + row] = pr[q].x;
                    Asf[(kp + 1) * 68 + row] = pr[q].y;
                    Asf[(kp + 2) * 68 + row] = pr[q].z;
                    Asf[(kp + 3) * 68 + row] = pr[q].w;
                }
                __syncthreads();
                if (c < 15) {
                    #pragma unroll
                    for (int q = 0; q < 2; q++) {
                        int f = tid + q * 256; int row = f >> 3, kp = (f & 7) * 4;
                        pr[q] = __ldcg((const float4*)(g_RH + (size_t)(bB0 + row) * Hsz + (c + 1) * 32 + kp));
                    }
                }
                const float* wbase = WBf + c * 32 * 32;
                #pragma unroll
                for (int kk = 0; kk < 32; kk++) {
                    float2 a = *(const float2*)(Asf + kk * 68 + ty * 2);
                    float4 b = *(const float4*)(wbase + kk * 32 + tx * 4);
                    ull bb0 = pk2(b.x, b.y), bb1 = pk2(b.z, b.w);
                    ull a0 = pk2(a.x, a.x), a1 = pk2(a.y, a.y);
                    fma2(acc[0][0], a0, bb0); fma2(acc[0][1], a0, bb1);
                    fma2(acc[1][0], a1, bb0); fma2(acc[1][1], a1, bb1);
                }
            }
            // epilogue: h = (1-z)*hd + z*tanh(An + acc)
            const float* An = g_A + 2 * TBH + (size_t)t * BH;
            #pragma unroll
            for (int i = 0; i < 2; i++) {
                int b = bB0 + ty * 2 + i;
                #pragma unroll
                for (int p = 0; p < 2; p++) {
                    float lo, hi; upk(acc[i][p], lo, hi);
                    int j = jB0 + tx * 4 + p * 2;
                    size_t o = (size_t)b * Hsz + j;
                    float ht0 = tanhf(lo + An[o]);
                    float ht1 = tanhf(hi + An[o + 1]);
                    float z0 = __ldcg(g_Z + o), z1 = __ldcg(g_Z + o + 1);
                    float hv0 = gh[o]     * __ldcg(g_hbuf + o);
                    float hv1 = gh[o + 1] * __ldcg(g_hbuf + o + 1);
                    g_hbuf[o]     = (1.f - z0) * hv0 + z0 * ht0;
                    g_hbuf[o + 1] = (1.f - z1) * hv1 + z1 * ht1;
                }
            }
        }
        gsync(target);
    }

    // copy final h to output
    for (int i = tid; i < 2048; i += 256)
        out[cta * 2048 + i] = __ldcg(g_hbuf + cta * 2048 + i);
}

// ---------------- launch ----------------
extern "C" void kernel_launch(void* const* d_in, const int* in_sizes, int n_in,
                              void* d_out, int out_size) {
    const float* x    = (const float*)d_in[0];
    const float* xl   = (const float*)d_in[1];
    const float* mk   = (const float*)d_in[2];
    const float* dl   = (const float*)d_in[3];
    const float* xm   = (const float*)d_in[4];
    const float* Wz   = (const float*)d_in[5];
    const float* bz   = (const float*)d_in[6];
    const float* Wr   = (const float*)d_in[7];
    const float* br   = (const float*)d_in[8];
    const float* Wn   = (const float*)d_in[9];
    const float* bn   = (const float*)d_in[10];
    const float* Wgx  = (const float*)d_in[11];
    const float* bgx  = (const float*)d_in[12];
    const float* Wgh  = (const float*)d_in[13];
    const float* bgh  = (const float*)d_in[14];

    static int smem_set = 0;
    if (!smem_set) {
        cudaFuncSetAttribute(loop_kernel,
                             cudaFuncAttributeMaxDynamicSharedMemorySize, 205312);
        smem_set = 1;
    }

    p0_kernel<<<(TB * Dsz) / 256, 256>>>(x, xl, mk, dl, xm, Wgx, bgx);
    p1_kernel<<<dim3(TB / 128, Hsz / 128, 3), 256>>>(Wz, bz, Wr, br, Wn, bn);
    p2_kernel<<<dim3(TB / 128, Hsz / 128), 256>>>(Wgh, bgh);
    zero_bar_kernel<<<1, 1>>>();
    loop_kernel<<<NCTA, 256, 205312>>>(Wz, Wr, Wn, (float*)d_out);
}

// round 4
// speedup vs baseline: 2.1952x; 1.3472x over previous
#include <cuda_runtime.h>
#include <cuda_bf16.h>
#include <cstdint>

#define Bsz 512
#define Tsz 256
#define Dsz 128
#define Hsz 512
#define GIN 768
#define TB  (Tsz*Bsz)          /* 131072 */
#define BH  (Bsz*Hsz)          /* 262144 */
#define NCTA 128

static const size_t TBH = (size_t)TB * Hsz;   /* 67108864 */

// smem layout (bytes)
#define OFF_WAH 0u
#define OFF_WAL 66560u
#define OFF_WBH 133120u
#define OFF_WBL 166400u
#define OFF_ACT_H 199680u
#define OFF_ACT_L 208896u
#define SMEM_TOTAL 218112

// ---------------- scratch (__device__ globals: allocation-free) ----------------
__device__ float g_xm[50331648];        // (T*B, 384) = [x_tilde | mask | delta]
__device__ float g_A [201326592];       // 3 x (T*B, H): affine terms (bias incl.)
__device__ float g_gh[67108864];        // (T*B, H): hidden decay gamma_h
__device__ float g_HD[BH];              // hd = gh*h (fp32)
__device__ float g_Z [BH];              // z gate
__device__ __nv_bfloat16 g_hd_hi[BH], g_hd_lo[BH];   // hd bf16 splits
__device__ __nv_bfloat16 g_rh_hi[BH], g_rh_lo[BH];   // r*hd bf16 splits
__device__ __nv_bfloat16 g_W_hi[3*Hsz*Hsz], g_W_lo[3*Hsz*Hsz]; // U-slices, [g][j][k]
__device__ unsigned g_barrier;

// ---------------- small helpers ----------------
typedef unsigned long long ull;
__device__ __forceinline__ ull pk2(float lo, float hi) {
    ull r; asm("mov.b64 %0,{%1,%2};" : "=l"(r) : "f"(lo), "f"(hi)); return r;
}
__device__ __forceinline__ void fma2(ull &c, ull a, ull b) {
    asm("fma.rn.f32x2 %0,%1,%2,%0;" : "+l"(c) : "l"(a), "l"(b));
}
__device__ __forceinline__ void upk(ull v, float &lo, float &hi) {
    asm("mov.b64 {%0,%1},%2;" : "=f"(lo), "=f"(hi) : "l"(v));
}
__device__ __forceinline__ float sigm(float x) { return 1.f / (1.f + expf(-x)); }

__device__ __forceinline__ uint32_t smem_u32(const void* p) {
    uint32_t a;
    asm("{ .reg .u64 t; cvta.to.shared.u64 t, %1; cvt.u32.u64 %0, t; }" : "=r"(a) : "l"(p));
    return a;
}
__device__ __forceinline__ void cpa16(uint32_t dst, const void* src) {
    asm volatile("cp.async.cg.shared.global [%0],[%1],16;" :: "r"(dst), "l"(src));
}
__device__ __forceinline__ void sts16(uint32_t a, uint4 v) {
    asm volatile("st.shared.v4.b32 [%0],{%1,%2,%3,%4};"
                 :: "r"(a), "r"(v.x), "r"(v.y), "r"(v.z), "r"(v.w));
}
__device__ __forceinline__ void ldsm4(uint32_t &r0, uint32_t &r1, uint32_t &r2,
                                      uint32_t &r3, uint32_t addr) {
    asm volatile("ldmatrix.sync.aligned.m8n8.x4.shared.b16 {%0,%1,%2,%3},[%4];"
                 : "=r"(r0), "=r"(r1), "=r"(r2), "=r"(r3) : "r"(addr));
}
__device__ __forceinline__ void mma_bf16(float* d, uint32_t a0, uint32_t a1,
                                         uint32_t a2, uint32_t a3,
                                         uint32_t b0, uint32_t b1) {
    asm volatile("mma.sync.aligned.m16n8k16.row.col.f32.bf16.bf16.f32 "
                 "{%0,%1,%2,%3},{%4,%5,%6,%7},{%8,%9},{%0,%1,%2,%3};"
                 : "+f"(d[0]), "+f"(d[1]), "+f"(d[2]), "+f"(d[3])
                 : "r"(a0), "r"(a1), "r"(a2), "r"(a3), "r"(b0), "r"(b1));
}

// ---------------- grid barrier ----------------
__device__ __forceinline__ void gsync(unsigned &target) {
    __syncthreads();
    __threadfence();
    if (threadIdx.x == 0) {
        atomicAdd(&g_barrier, 1u);
        while (*((volatile unsigned*)&g_barrier) < target) { }
    }
    __syncthreads();
    target += NCTA;
}
__global__ void zero_bar_kernel() { g_barrier = 0u; }

// ---------------- P0: elementwise input-decay / staging ----------------
__global__ void p0_kernel(const float* __restrict__ x,  const float* __restrict__ xl,
                          const float* __restrict__ mk, const float* __restrict__ dl,
                          const float* __restrict__ xmean,
                          const float* __restrict__ Wgx, const float* __restrict__ bgx) {
    int idx = blockIdx.x * 256 + threadIdx.x;
    int d   = idx & 127;
    int row = idx >> 7;
    int t   = row >> 9;
    int b   = row & 511;
    size_t xi = ((size_t)b * Tsz + t) * Dsz + d;
    float dv = dl[xi], mv = mk[xi];
    float gx = expf(-fmaxf(0.f, dv * Wgx[d * Dsz + d] + bgx[d]));
    float xt = mv * x[xi] + (1.f - mv) * (gx * xl[xi] + (1.f - gx) * xmean[d]);
    size_t o = (size_t)row * 384;
    g_xm[o + d]       = xt;
    g_xm[o + 128 + d] = mv;
    g_xm[o + 256 + d] = dv;
}

// ---------------- prep: split hidden-weight slices into bf16 hi/lo ------------
__global__ void prep_w_kernel(const float* __restrict__ Wz, const float* __restrict__ Wr,
                              const float* __restrict__ Wn) {
    int idx = blockIdx.x * 256 + threadIdx.x;     // g*2^18 + j*512 + k
    int k = idx & 511, j = (idx >> 9) & 511, g = idx >> 18;
    const float* W = (g == 0) ? Wz : (g == 1) ? Wr : Wn;
    float w = W[(size_t)j * GIN + 128 + k];
    __nv_bfloat16 hi = __float2bfloat16(w);
    __nv_bfloat16 lo = __float2bfloat16(w - __bfloat162float(hi));
    g_W_hi[idx] = hi;
    g_W_lo[idx] = lo;
}

// ---------------- P1: A_s = [xt|m] @ W_s[:, {0:128,640:768}].T + b_s ----------
__global__ __launch_bounds__(256) void p1_kernel(
        const float* __restrict__ Wz, const float* __restrict__ bz,
        const float* __restrict__ Wr, const float* __restrict__ br,
        const float* __restrict__ Wn, const float* __restrict__ bn) {
    int s = blockIdx.z;
    const float* W    = (s == 0) ? Wz : (s == 1) ? Wr : Wn;
    const float* bias = (s == 0) ? bz : (s == 1) ? br : bn;
    float* out = g_A + (size_t)s * TBH;
    int r0 = blockIdx.x * 128, j0 = blockIdx.y * 128;
    __shared__ float As[16][132];
    __shared__ float Bs[16][132];
    int tid = threadIdx.x, tx = tid & 15, ty = tid >> 4;
    ull acc[8][4];
    #pragma unroll
    for (int i = 0; i < 8; i++)
        #pragma unroll
        for (int j = 0; j < 4; j++) acc[i][j] = 0ull;

    for (int k0 = 0; k0 < 256; k0 += 16) {
        #pragma unroll
        for (int u = 0; u < 8; u++) {
            int e = tid + u * 256;
            int k = e & 15, row = e >> 4;
            As[k][row] = g_xm[(size_t)(r0 + row) * 384 + (k0 + k)];
            int kq  = k0 + k;
            int col = (kq < 128) ? kq : kq + 512;
            Bs[k][row] = W[(size_t)(j0 + row) * GIN + col];
        }
        __syncthreads();
        #pragma unroll
        for (int kk = 0; kk < 16; kk++) {
            float4 a0 = *(const float4*)&As[kk][ty * 8];
            float4 a1 = *(const float4*)&As[kk][ty * 8 + 4];
            float4 b0 = *(const float4*)&Bs[kk][tx * 8];
            float4 b1 = *(const float4*)&Bs[kk][tx * 8 + 4];
            ull bb[4] = { pk2(b0.x,b0.y), pk2(b0.z,b0.w), pk2(b1.x,b1.y), pk2(b1.z,b1.w) };
            ull aa[8] = { pk2(a0.x,a0.x), pk2(a0.y,a0.y), pk2(a0.z,a0.z), pk2(a0.w,a0.w),
                          pk2(a1.x,a1.x), pk2(a1.y,a1.y), pk2(a1.z,a1.z), pk2(a1.w,a1.w) };
            #pragma unroll
            for (int i = 0; i < 8; i++)
                #pragma unroll
                for (int j = 0; j < 4; j++) fma2(acc[i][j], aa[i], bb[j]);
        }
        __syncthreads();
    }
    #pragma unroll
    for (int i = 0; i < 8; i++) {
        size_t r = (size_t)(r0 + ty * 8 + i);
        #pragma unroll
        for (int j4 = 0; j4 < 4; j4++) {
            float lo, hi; upk(acc[i][j4], lo, hi);
            int j = j0 + tx * 8 + j4 * 2;
            out[r * Hsz + j]     = lo + bias[j];
            out[r * Hsz + j + 1] = hi + bias[j + 1];
        }
    }
}

// ---------------- P2: gh = exp(-relu(delta @ Wgh.T + bgh)) --------------------
__global__ __launch_bounds__(256) void p2_kernel(const float* __restrict__ Wgh,
                                                 const float* __restrict__ bgh) {
    int r0 = blockIdx.x * 128, j0 = blockIdx.y * 128;
    __shared__ float As[16][132];
    __shared__ float Bs[16][132];
    int tid = threadIdx.x, tx = tid & 15, ty = tid >> 4;
    ull acc[8][4];
    #pragma unroll
    for (int i = 0; i < 8; i++)
        #pragma unroll
        for (int j = 0; j < 4; j++) acc[i][j] = 0ull;

    for (int k0 = 0; k0 < 128; k0 += 16) {
        #pragma unroll
        for (int u = 0; u < 8; u++) {
            int e = tid + u * 256;
            int k = e & 15, row = e >> 4;
            As[k][row] = g_xm[(size_t)(r0 + row) * 384 + 256 + (k0 + k)];
            Bs[k][row] = Wgh[(size_t)(j0 + row) * Dsz + (k0 + k)];
        }
        __syncthreads();
        #pragma unroll
        for (int kk = 0; kk < 16; kk++) {
            float4 a0 = *(const float4*)&As[kk][ty * 8];
            float4 a1 = *(const float4*)&As[kk][ty * 8 + 4];
            float4 b0 = *(const float4*)&Bs[kk][tx * 8];
            float4 b1 = *(const float4*)&Bs[kk][tx * 8 + 4];
            ull bb[4] = { pk2(b0.x,b0.y), pk2(b0.z,b0.w), pk2(b1.x,b1.y), pk2(b1.z,b1.w) };
            ull aa[8] = { pk2(a0.x,a0.x), pk2(a0.y,a0.y), pk2(a0.z,a0.z), pk2(a0.w,a0.w),
                          pk2(a1.x,a1.x), pk2(a1.y,a1.y), pk2(a1.z,a1.z), pk2(a1.w,a1.w) };
            #pragma unroll
            for (int i = 0; i < 8; i++)
                #pragma unroll
                for (int j = 0; j < 4; j++) fma2(acc[i][j], aa[i], bb[j]);
        }
        __syncthreads();
    }
    #pragma unroll
    for (int i = 0; i < 8; i++) {
        size_t r = (size_t)(r0 + ty * 8 + i);
        #pragma unroll
        for (int j4 = 0; j4 < 4; j4++) {
            float lo, hi; upk(acc[i][j4], lo, hi);
            int j = j0 + tx * 8 + j4 * 2;
            g_gh[r * Hsz + j]     = expf(-fmaxf(0.f, lo + bgh[j]));
            g_gh[r * Hsz + j + 1] = expf(-fmaxf(0.f, hi + bgh[j + 1]));
        }
    }
}

// ---------------- bf16x3 MMA GEMM over K=512 (8 chunks of 64) -----------------
// out tile: 64 rows x NF*16 cols per CTA; warp = 16 rows x NF*8 cols.
// Weights resident in smem (wh/wl, 1040B row stride); activations staged per
// chunk into OFF_ACT (144B row stride) with register prefetch from global.
template<int NF>
__device__ __forceinline__ void run_gemm(uint32_t sb, uint32_t wh, uint32_t wl,
        const __nv_bfloat16* __restrict__ gah, const __nv_bfloat16* __restrict__ gal,
        int r0, int tid, float (*d)[4]) {
    #pragma unroll
    for (int nf = 0; nf < NF; nf++)
        #pragma unroll
        for (int i = 0; i < 4; i++) d[nf][i] = 0.f;

    int wid = tid >> 5, l = tid & 31;
    int wr0 = (wid >> 1) * 16;
    int wn0 = (wid & 1) * (NF * 8);
    uint32_t Ah = sb + OFF_ACT_H, Al = sb + OFF_ACT_L;
    uint32_t aoff  = (uint32_t)((wr0 + (l & 15)) * 144 + ((l >> 4) * 8) * 2);
    uint32_t boff  = (uint32_t)((wn0 + ((l >> 4) << 3) + (l & 7)) * 1040
                                + (((l >> 3) & 1) * 8) * 2);
    uint32_t so0 = (uint32_t)((tid >> 3) * 144 + (tid & 7) * 16);
    uint32_t so1 = (uint32_t)(((tid + 256) >> 3) * 144 + (tid & 7) * 16);

    const __nv_bfloat16* sh0 = gah + (size_t)(r0 + (tid >> 3)) * Hsz + (tid & 7) * 8;
    const __nv_bfloat16* sh1 = gah + (size_t)(r0 + ((tid + 256) >> 3)) * Hsz + (tid & 7) * 8;
    const __nv_bfloat16* sl0 = gal + (size_t)(r0 + (tid >> 3)) * Hsz + (tid & 7) * 8;
    const __nv_bfloat16* sl1 = gal + (size_t)(r0 + ((tid + 256) >> 3)) * Hsz + (tid & 7) * 8;

    uint4 pf0 = __ldcg((const uint4*)sh0);
    uint4 pf1 = __ldcg((const uint4*)sh1);
    uint4 pf2 = __ldcg((const uint4*)sl0);
    uint4 pf3 = __ldcg((const uint4*)sl1);

    for (int c = 0; c < 8; c++) {
        sts16(Ah + so0, pf0); sts16(Ah + so1, pf1);
        sts16(Al + so0, pf2); sts16(Al + so1, pf3);
        __syncthreads();
        if (c < 7) {
            pf0 = __ldcg((const uint4*)(sh0 + (c + 1) * 64));
            pf1 = __ldcg((const uint4*)(sh1 + (c + 1) * 64));
            pf2 = __ldcg((const uint4*)(sl0 + (c + 1) * 64));
            pf3 = __ldcg((const uint4*)(sl1 + (c + 1) * 64));
        }
        #pragma unroll
        for (int ks = 0; ks < 4; ks++) {
            uint32_t ka = (uint32_t)(ks * 32);
            uint32_t kb = (uint32_t)((c * 64 + ks * 16) * 2);
            uint32_t ah0, ah1, ah2, ah3, al0, al1, al2, al3;
            ldsm4(ah0, ah1, ah2, ah3, Ah + aoff + ka);
            ldsm4(al0, al1, al2, al3, Al + aoff + ka);
            #pragma unroll
            for (int g2 = 0; g2 < NF / 2; g2++) {
                uint32_t bo = boff + (uint32_t)(g2 * 16 * 1040) + kb;
                uint32_t bh0, bh1, bh2, bh3, bl0, bl1, bl2, bl3;
                ldsm4(bh0, bh1, bh2, bh3, sb + wh + bo);
                ldsm4(bl0, bl1, bl2, bl3, sb + wl + bo);
                mma_bf16(d[2*g2],     ah0, ah1, ah2, ah3, bh0, bh1);
                mma_bf16(d[2*g2 + 1], ah0, ah1, ah2, ah3, bh2, bh3);
                mma_bf16(d[2*g2],     ah0, ah1, ah2, ah3, bl0, bl1);
                mma_bf16(d[2*g2 + 1], ah0, ah1, ah2, ah3, bl2, bl3);
                mma_bf16(d[2*g2],     al0, al1, al2, al3, bh0, bh1);
                mma_bf16(d[2*g2 + 1], al0, al1, al2, al3, bh2, bh3);
            }
        }
        __syncthreads();
    }
}

// ---------------- persistent recurrent loop kernel ----------------------------
__global__ __launch_bounds__(256, 1) void loop_kernel(float* __restrict__ out) {
    extern __shared__ char smem[];
    uint32_t sb = smem_u32(smem);
    int tid = threadIdx.x, cta = blockIdx.x;
    int wid = tid >> 5, l = tid & 31, g = l >> 2, tg = l & 3;

    // roles
    int sA  = cta >> 6;                       // 0 = z, 1 = r
    int tA  = cta & 63;
    int rA0 = (tA >> 3) * 64, jA0 = (tA & 7) * 64;
    int rB0 = (cta >> 4) * 64, jB0 = (cta & 15) * 32;
    const __nv_bfloat16* WAhi = g_W_hi + (size_t)sA * Hsz * Hsz;
    const __nv_bfloat16* WAlo = g_W_lo + (size_t)sA * Hsz * Hsz;
    const __nv_bfloat16* WBhi = g_W_hi + (size_t)2 * Hsz * Hsz;
    const __nv_bfloat16* WBlo = g_W_lo + (size_t)2 * Hsz * Hsz;

    // one-time: weights into smem (1040B row stride, conflict-free for LDSM)
    for (int i = tid; i < 4096; i += 256) {
        int r = i >> 6, s = i & 63;
        uint32_t d0 = sb + OFF_WAH + r * 1040 + s * 16;
        cpa16(d0,                      WAhi + (size_t)(jA0 + r) * Hsz + s * 8);
        cpa16(d0 + (OFF_WAL - OFF_WAH), WAlo + (size_t)(jA0 + r) * Hsz + s * 8);
    }
    for (int i = tid; i < 2048; i += 256) {
        int r = i >> 6, s = i & 63;
        uint32_t d0 = sb + OFF_WBH + r * 1040 + s * 16;
        cpa16(d0,                      WBhi + (size_t)(jB0 + r) * Hsz + s * 8);
        cpa16(d0 + (OFF_WBL - OFF_WBH), WBlo + (size_t)(jB0 + r) * Hsz + s * 8);
    }
    asm volatile("cp.async.commit_group;" ::: "memory");
    asm volatile("cp.async.wait_group 0;" ::: "memory");

    // zero-init h-derived buffers (h0 = 0)
    __nv_bfloat16 zb = __float2bfloat16(0.f);
    for (int i = tid; i < 2048; i += 256) {
        int o = cta * 2048 + i;
        g_HD[o] = 0.f;
        g_hd_hi[o] = zb;
        g_hd_lo[o] = zb;
    }
    unsigned target = NCTA;
    gsync(target);

    int wr0 = (wid >> 1) * 16;

    for (int t = 0; t < Tsz; t++) {
        // ========== phase A ==========
        {
            float d[4][4];
            run_gemm<4>(sb, OFF_WAH, OFF_WAL, g_hd_hi, g_hd_lo, rA0, tid, d);
            int wn0 = (wid & 1) * 32;
            const float* At = g_A + (size_t)sA * TBH + (size_t)t * BH;
            #pragma unroll
            for (int nf = 0; nf < 4; nf++) {
                int col = jA0 + wn0 + nf * 8 + tg * 2;
                #pragma unroll
                for (int h = 0; h < 2; h++) {
                    int row = rA0 + wr0 + g + h * 8;
                    size_t o = (size_t)row * Hsz + col;
                    float v0 = d[nf][h * 2], v1 = d[nf][h * 2 + 1];
                    float s0 = sigm(v0 + At[o]);
                    float s1 = sigm(v1 + At[o + 1]);
                    if (sA == 0) {
                        float2 zz = {s0, s1};
                        *(float2*)(g_Z + o) = zz;
                    } else {
                        float h0 = __ldcg(g_HD + o), h1 = __ldcg(g_HD + o + 1);
                        float r0v = s0 * h0, r1v = s1 * h1;
                        __nv_bfloat16 hh0 = __float2bfloat16(r0v);
                        __nv_bfloat16 hh1 = __float2bfloat16(r1v);
                        __nv_bfloat162 hp; hp.x = hh0; hp.y = hh1;
                        __nv_bfloat162 lp;
                        lp.x = __float2bfloat16(r0v - __bfloat162float(hh0));
                        lp.y = __float2bfloat16(r1v - __bfloat162float(hh1));
                        *(__nv_bfloat162*)(g_rh_hi + o) = hp;
                        *(__nv_bfloat162*)(g_rh_lo + o) = lp;
                    }
                }
            }
        }
        gsync(target);

        // ========== phase B ==========
        {
            float d[2][4];
            run_gemm<2>(sb, OFF_WBH, OFF_WBL, g_rh_hi, g_rh_lo, rB0, tid, d);
            int wn0 = (wid & 1) * 16;
            const float* An = g_A + (size_t)2 * TBH + (size_t)t * BH;
            const float* ghn = g_gh + (size_t)(t + 1) * BH;
            bool last = (t == Tsz - 1);
            #pragma unroll
            for (int nf = 0; nf < 2; nf++) {
                int col = jB0 + wn0 + nf * 8 + tg * 2;
                #pragma unroll
                for (int h = 0; h < 2; h++) {
                    int row = rB0 + wr0 + g + h * 8;
                    size_t o = (size_t)row * Hsz + col;
                    #pragma unroll
                    for (int q = 0; q < 2; q++) {
                        float ht = tanhf(d[nf][h * 2 + q] + An[o + q]);
                        float z  = __ldcg(g_Z + o + q);
                        float hd = __ldcg(g_HD + o + q);
                        float hp = (1.f - z) * hd + z * ht;
                        if (last) {
                            out[o + q] = hp;
                        } else {
                            float hdn = ghn[o + q] * hp;
                            g_HD[o + q] = hdn;
                            __nv_bfloat16 hh = __float2bfloat16(hdn);
                            g_hd_hi[o + q] = hh;
                            g_hd_lo[o + q] = __float2bfloat16(hdn - __bfloat162float(hh));
                        }
                    }
                }
            }
        }
        gsync(target);
    }
}

// ---------------- launch ----------------
extern "C" void kernel_launch(void* const* d_in, const int* in_sizes, int n_in,
                              void* d_out, int out_size) {
    const float* x    = (const float*)d_in[0];
    const float* xl   = (const float*)d_in[1];
    const float* mk   = (const float*)d_in[2];
    const float* dl   = (const float*)d_in[3];
    const float* xm   = (const float*)d_in[4];
    const float* Wz   = (const float*)d_in[5];
    const float* bz   = (const float*)d_in[6];
    const float* Wr   = (const float*)d_in[7];
    const float* br   = (const float*)d_in[8];
    const float* Wn   = (const float*)d_in[9];
    const float* bn   = (const float*)d_in[10];
    const float* Wgx  = (const float*)d_in[11];
    const float* bgx  = (const float*)d_in[12];
    const float* Wgh  = (const float*)d_in[13];
    const float* bgh  = (const float*)d_in[14];

    static int smem_set = 0;
    if (!smem_set) {
        cudaFuncSetAttribute(loop_kernel,
                             cudaFuncAttributeMaxDynamicSharedMemorySize, SMEM_TOTAL);
        smem_set = 1;
    }

    p0_kernel<<<(TB * Dsz) / 256, 256>>>(x, xl, mk, dl, xm, Wgx, bgx);
    prep_w_kernel<<<(3 * Hsz * Hsz) / 256, 256>>>(Wz, Wr, Wn);
    p1_kernel<<<dim3(TB / 128, Hsz / 128, 3), 256>>>(Wz, bz, Wr, br, Wn, bn);
    p2_kernel<<<dim3(TB / 128, Hsz / 128), 256>>>(Wgh, bgh);
    zero_bar_kernel<<<1, 1>>>();
    loop_kernel<<<NCTA, 256, SMEM_TOTAL>>>((float*)d_out);
}

// round 5
// speedup vs baseline: 2.7703x; 1.2620x over previous
#include <cuda_runtime.h>
#include <cuda_bf16.h>
#include <cstdint>

#define Bsz 512
#define Tsz 256
#define Dsz 128
#define Hsz 512
#define GIN 768
#define TB  (Tsz*Bsz)          /* 131072 */
#define BH  (Bsz*Hsz)          /* 262144 */
#define NCTA 128

static const size_t TBH = (size_t)TB * Hsz;   /* 67108864 */

// loop-kernel smem layout (bytes)
#define OFF_WAH 0u
#define OFF_WAL 66560u
#define OFF_WBH 133120u
#define OFF_WBL 166400u
#define OFF_ACT_H 199680u
#define OFF_ACT_L 208896u
#define SMEM_TOTAL 218112

// precompute-gemm smem: 2 bufs x 4 tiles x (128 rows x 144B)
#define PG_TILE 18432u
#define PG_BUF  73728u
#define PG_SMEM 147456

// ---------------- scratch (__device__ globals: allocation-free) ----------------
__device__ float g_A [201326592];       // 3 x (T*B, H): affine terms (bias incl.)
__device__ float g_gh[67108864];        // (T*B, H): hidden decay gamma_h
__device__ float g_HD[BH];              // hd = gh*h (fp32)
__device__ float g_Z [BH];              // z gate
__device__ __nv_bfloat16 g_x1h[TB*256], g_x1l[TB*256];   // [xt|m] bf16 splits
__device__ __nv_bfloat16 g_dh [TB*128], g_dl [TB*128];   // delta bf16 splits
__device__ __nv_bfloat16 g_hd_hi[BH], g_hd_lo[BH];       // hd bf16 splits
__device__ __nv_bfloat16 g_rh_hi[BH], g_rh_lo[BH];       // r*hd bf16 splits
__device__ __nv_bfloat16 g_W_hi[3*Hsz*Hsz], g_W_lo[3*Hsz*Hsz];   // hidden slices
__device__ __nv_bfloat16 g_W1h[3*Hsz*256], g_W1l[3*Hsz*256];     // x|m slices
__device__ __nv_bfloat16 g_Wghh[Hsz*128], g_Wghl[Hsz*128];       // Wgh
__device__ unsigned g_barrier;

// ---------------- small helpers ----------------
__device__ __forceinline__ float sigm(float x) { return 1.f / (1.f + expf(-x)); }
__device__ __forceinline__ uint32_t smem_u32(const void* p) {
    uint32_t a;
    asm("{ .reg .u64 t; cvta.to.shared.u64 t, %1; cvt.u32.u64 %0, t; }" : "=r"(a) : "l"(p));
    return a;
}
__device__ __forceinline__ void cpa16(uint32_t dst, const void* src) {
    asm volatile("cp.async.cg.shared.global [%0],[%1],16;" :: "r"(dst), "l"(src));
}
__device__ __forceinline__ void sts16(uint32_t a, uint4 v) {
    asm volatile("st.shared.v4.b32 [%0],{%1,%2,%3,%4};"
                 :: "r"(a), "r"(v.x), "r"(v.y), "r"(v.z), "r"(v.w));
}
__device__ __forceinline__ void ldsm4(uint32_t &r0, uint32_t &r1, uint32_t &r2,
                                      uint32_t &r3, uint32_t addr) {
    asm volatile("ldmatrix.sync.aligned.m8n8.x4.shared.b16 {%0,%1,%2,%3},[%4];"
                 : "=r"(r0), "=r"(r1), "=r"(r2), "=r"(r3) : "r"(addr));
}
__device__ __forceinline__ void mma_bf16(float* d, uint32_t a0, uint32_t a1,
                                         uint32_t a2, uint32_t a3,
                                         uint32_t b0, uint32_t b1) {
    asm volatile("mma.sync.aligned.m16n8k16.row.col.f32.bf16.bf16.f32 "
                 "{%0,%1,%2,%3},{%4,%5,%6,%7},{%8,%9},{%0,%1,%2,%3};"
                 : "+f"(d[0]), "+f"(d[1]), "+f"(d[2]), "+f"(d[3])
                 : "r"(a0), "r"(a1), "r"(a2), "r"(a3), "r"(b0), "r"(b1));
}

// ---------------- grid barrier ----------------
__device__ __forceinline__ void gsync(unsigned &target) {
    __syncthreads();
    __threadfence();
    if (threadIdx.x == 0) {
        atomicAdd(&g_barrier, 1u);
        while (*((volatile unsigned*)&g_barrier) < target) { }
    }
    __syncthreads();
    target += NCTA;
}
__global__ void zero_bar_kernel() { g_barrier = 0u; }

// ---------------- P0: elementwise input-decay / staging (bf16 splits) ---------
__global__ void p0_kernel(const float* __restrict__ x,  const float* __restrict__ xl,
                          const float* __restrict__ mk, const float* __restrict__ dl,
                          const float* __restrict__ xmean,
                          const float* __restrict__ Wgx, const float* __restrict__ bgx) {
    int idx = blockIdx.x * 256 + threadIdx.x;
    int d   = idx & 127;
    int row = idx >> 7;
    int t   = row >> 9;
    int b   = row & 511;
    size_t xi = ((size_t)b * Tsz + t) * Dsz + d;
    float dv = dl[xi], mv = mk[xi];
    float gx = expf(-fmaxf(0.f, dv * Wgx[d * Dsz + d] + bgx[d]));
    float xt = mv * x[xi] + (1.f - mv) * (gx * xl[xi] + (1.f - gx) * xmean[d]);

    __nv_bfloat16 xh = __float2bfloat16(xt);
    g_x1h[(size_t)row * 256 + d] = xh;
    g_x1l[(size_t)row * 256 + d] = __float2bfloat16(xt - __bfloat162float(xh));
    g_x1h[(size_t)row * 256 + 128 + d] = __float2bfloat16(mv);   // exact (0/1)
    g_x1l[(size_t)row * 256 + 128 + d] = __float2bfloat16(0.f);
    __nv_bfloat16 dh = __float2bfloat16(dv);
    g_dh[(size_t)row * 128 + d] = dh;
    g_dl[(size_t)row * 128 + d] = __float2bfloat16(dv - __bfloat162float(dh));
}

// ---------------- prep: split weights into bf16 hi/lo -------------------------
__global__ void prep_w_kernel(const float* __restrict__ Wz, const float* __restrict__ Wr,
                              const float* __restrict__ Wn, const float* __restrict__ Wgh) {
    int idx = blockIdx.x * 256 + threadIdx.x;
    float w;
    __nv_bfloat16 *ph, *pl;
    if (idx < 786432) {                 // hidden slices: g*2^18 + j*512 + k
        int k = idx & 511, j = (idx >> 9) & 511, g = idx >> 18;
        const float* W = (g == 0) ? Wz : (g == 1) ? Wr : Wn;
        w = W[(size_t)j * GIN + 128 + k];
        ph = g_W_hi + idx; pl = g_W_lo + idx;
    } else if (idx < 786432 + 393216) { // x|m slices: g*(512*256) + j*256 + k
        int e = idx - 786432;
        int k = e & 255, j = (e >> 8) & 511, g = e >> 17;
        const float* W = (g == 0) ? Wz : (g == 1) ? Wr : Wn;
        int col = (k < 128) ? k : (512 + k);
        w = W[(size_t)j * GIN + col];
        ph = g_W1h + e; pl = g_W1l + e;
    } else if (idx < 786432 + 393216 + 65536) {
        int e = idx - 786432 - 393216;  // j*128 + k
        w = Wgh[e];
        ph = g_Wghh + e; pl = g_Wghl + e;
    } else return;
    __nv_bfloat16 hi = __float2bfloat16(w);
    *ph = hi;
    *pl = __float2bfloat16(w - __bfloat162float(hi));
}

// ---------------- precompute GEMM core (bf16x3, 128x128 tile, K chunks of 64) -
// d[2][16][...] accumulators: warp 32 rows x 64 cols -> 2 m-tiles x 8 n-frags
template<int KCH>
__device__ __forceinline__ void pg_core(uint32_t sb,
        const __nv_bfloat16* __restrict__ Ah, const __nv_bfloat16* __restrict__ Al,
        const __nv_bfloat16* __restrict__ Bh, const __nv_bfloat16* __restrict__ Bl,
        int row0, int j0, int K, int tid, float d[2][8][4]) {
    #pragma unroll
    for (int mt = 0; mt < 2; mt++)
        #pragma unroll
        for (int nf = 0; nf < 8; nf++)
            #pragma unroll
            for (int i = 0; i < 4; i++) d[mt][nf][i] = 0.f;

    int wid = tid >> 5, l = tid & 31;
    int wr0 = (wid >> 1) * 32;
    int wn0 = (wid & 1) * 64;
    uint32_t aoff = (uint32_t)((wr0 + (l & 15)) * 144 + ((l >> 4) * 8) * 2);
    uint32_t boff = (uint32_t)((wn0 + ((l >> 4) << 3) + (l & 7)) * 144
                               + (((l >> 3) & 1) * 8) * 2);
    int sr = tid >> 3, ss = tid & 7;

    // prologue: chunk 0 -> buf0
    #pragma unroll
    for (int u = 0; u < 4; u++) {
        int r = sr + u * 32;
        uint32_t db = sb + (uint32_t)(r * 144 + ss * 16);
        cpa16(db,               Ah + (size_t)(row0 + r) * K + ss * 8);
        cpa16(db + PG_TILE,     Al + (size_t)(row0 + r) * K + ss * 8);
        cpa16(db + 2 * PG_TILE, Bh + (size_t)(j0 + r) * K + ss * 8);
        cpa16(db + 3 * PG_TILE, Bl + (size_t)(j0 + r) * K + ss * 8);
    }
    asm volatile("cp.async.commit_group;" ::: "memory");

    for (int c = 0; c < KCH; c++) {
        if (c + 1 < KCH) {
            uint32_t bb = sb + ((c + 1) & 1) * PG_BUF;
            #pragma unroll
            for (int u = 0; u < 4; u++) {
                int r = sr + u * 32;
                uint32_t db = bb + (uint32_t)(r * 144 + ss * 16);
                int ko = (c + 1) * 64 + ss * 8;
                cpa16(db,               Ah + (size_t)(row0 + r) * K + ko);
                cpa16(db + PG_TILE,     Al + (size_t)(row0 + r) * K + ko);
                cpa16(db + 2 * PG_TILE, Bh + (size_t)(j0 + r) * K + ko);
                cpa16(db + 3 * PG_TILE, Bl + (size_t)(j0 + r) * K + ko);
            }
            asm volatile("cp.async.commit_group;" ::: "memory");
            asm volatile("cp.async.wait_group 1;" ::: "memory");
        } else {
            asm volatile("cp.async.wait_group 0;" ::: "memory");
        }
        __syncthreads();
        uint32_t bb = sb + (c & 1) * PG_BUF;
        #pragma unroll
        for (int ks = 0; ks < 4; ks++) {
            uint32_t ko = (uint32_t)(ks * 32);
            uint32_t ah[2][4], al[2][4];
            #pragma unroll
            for (int mt = 0; mt < 2; mt++) {
                uint32_t a = bb + aoff + (uint32_t)(mt * 16 * 144) + ko;
                ldsm4(ah[mt][0], ah[mt][1], ah[mt][2], ah[mt][3], a);
                ldsm4(al[mt][0], al[mt][1], al[mt][2], al[mt][3], a + PG_TILE);
            }
            #pragma unroll
            for (int p = 0; p < 4; p++) {
                uint32_t b = bb + 2 * PG_TILE + boff + (uint32_t)(p * 16 * 144) + ko;
                uint32_t bh0, bh1, bh2, bh3, bl0, bl1, bl2, bl3;
                ldsm4(bh0, bh1, bh2, bh3, b);
                ldsm4(bl0, bl1, bl2, bl3, b + PG_TILE);
                #pragma unroll
                for (int mt = 0; mt < 2; mt++) {
                    mma_bf16(d[mt][2*p],   ah[mt][0], ah[mt][1], ah[mt][2], ah[mt][3], bh0, bh1);
                    mma_bf16(d[mt][2*p+1], ah[mt][0], ah[mt][1], ah[mt][2], ah[mt][3], bh2, bh3);
                    mma_bf16(d[mt][2*p],   ah[mt][0], ah[mt][1], ah[mt][2], ah[mt][3], bl0, bl1);
                    mma_bf16(d[mt][2*p+1], ah[mt][0], ah[mt][1], ah[mt][2], ah[mt][3], bl2, bl3);
                    mma_bf16(d[mt][2*p],   al[mt][0], al[mt][1], al[mt][2], al[mt][3], bh0, bh1);
                    mma_bf16(d[mt][2*p+1], al[mt][0], al[mt][1], al[mt][2], al[mt][3], bh2, bh3);
                }
            }
        }
        __syncthreads();
    }
}

// ---------------- P1 (MMA): A_s = [xt|m] @ W1_s^T + b_s -----------------------
__global__ __launch_bounds__(256, 1) void p1m_kernel(
        const float* __restrict__ bz, const float* __restrict__ br,
        const float* __restrict__ bn) {
    extern __shared__ char smem[];
    uint32_t sb = smem_u32(smem);
    int s = blockIdx.z, tid = threadIdx.x;
    int row0 = blockIdx.x * 128, j0 = blockIdx.y * 128;
    const float* bias = (s == 0) ? bz : (s == 1) ? br : bn;
    float* out = g_A + (size_t)s * TBH;
    float d[2][8][4];
    pg_core<4>(sb, g_x1h, g_x1l,
               g_W1h + (size_t)s * Hsz * 256, g_W1l + (size_t)s * Hsz * 256,
               row0, j0, 256, tid, d);
    int wid = tid >> 5, l = tid & 31;
    int wr0 = (wid >> 1) * 32, wn0 = (wid & 1) * 64;
    #pragma unroll
    for (int mt = 0; mt < 2; mt++)
        #pragma unroll
        for (int nf = 0; nf < 8; nf++)
            #pragma unroll
            for (int h = 0; h < 2; h++) {
                int row = row0 + wr0 + mt * 16 + (l >> 2) + h * 8;
                int col = j0 + wn0 + nf * 8 + (l & 3) * 2;
                float2 v;
                v.x = d[mt][nf][h * 2]     + bias[col];
                v.y = d[mt][nf][h * 2 + 1] + bias[col + 1];
                *(float2*)(out + (size_t)row * Hsz + col) = v;
            }
}

// ---------------- P2 (MMA): gh = exp(-relu(delta @ Wgh^T + bgh)) --------------
__global__ __launch_bounds__(256, 1) void p2m_kernel(const float* __restrict__ bgh) {
    extern __shared__ char smem[];
    uint32_t sb = smem_u32(smem);
    int tid = threadIdx.x;
    int row0 = blockIdx.x * 128, j0 = blockIdx.y * 128;
    float d[2][8][4];
    pg_core<2>(sb, g_dh, g_dl, g_Wghh, g_Wghl, row0, j0, 128, tid, d);
    int wid = tid >> 5, l = tid & 31;
    int wr0 = (wid >> 1) * 32, wn0 = (wid & 1) * 64;
    #pragma unroll
    for (int mt = 0; mt < 2; mt++)
        #pragma unroll
        for (int nf = 0; nf < 8; nf++)
            #pragma unroll
            for (int h = 0; h < 2; h++) {
                int row = row0 + wr0 + mt * 16 + (l >> 2) + h * 8;
                int col = j0 + wn0 + nf * 8 + (l & 3) * 2;
                float2 v;
                v.x = expf(-fmaxf(0.f, d[mt][nf][h * 2]     + bgh[col]));
                v.y = expf(-fmaxf(0.f, d[mt][nf][h * 2 + 1] + bgh[col + 1]));
                *(float2*)(g_gh + (size_t)row * Hsz + col) = v;
            }
}

// ---------------- loop-kernel bf16x3 GEMM (unchanged from R4) -----------------
template<int NF>
__device__ __forceinline__ void run_gemm(uint32_t sb, uint32_t wh, uint32_t wl,
        const __nv_bfloat16* __restrict__ gah, const __nv_bfloat16* __restrict__ gal,
        int r0, int tid, float (*d)[4]) {
    #pragma unroll
    for (int nf = 0; nf < NF; nf++)
        #pragma unroll
        for (int i = 0; i < 4; i++) d[nf][i] = 0.f;

    int wid = tid >> 5, l = tid & 31;
    int wr0 = (wid >> 1) * 16;
    int wn0 = (wid & 1) * (NF * 8);
    uint32_t Ah = sb + OFF_ACT_H, Al = sb + OFF_ACT_L;
    uint32_t aoff  = (uint32_t)((wr0 + (l & 15)) * 144 + ((l >> 4) * 8) * 2);
    uint32_t boff  = (uint32_t)((wn0 + ((l >> 4) << 3) + (l & 7)) * 1040
                                + (((l >> 3) & 1) * 8) * 2);
    uint32_t so0 = (uint32_t)((tid >> 3) * 144 + (tid & 7) * 16);
    uint32_t so1 = (uint32_t)(((tid + 256) >> 3) * 144 + (tid & 7) * 16);

    const __nv_bfloat16* sh0 = gah + (size_t)(r0 + (tid >> 3)) * Hsz + (tid & 7) * 8;
    const __nv_bfloat16* sh1 = gah + (size_t)(r0 + ((tid + 256) >> 3)) * Hsz + (tid & 7) * 8;
    const __nv_bfloat16* sl0 = gal + (size_t)(r0 + (tid >> 3)) * Hsz + (tid & 7) * 8;
    const __nv_bfloat16* sl1 = gal + (size_t)(r0 + ((tid + 256) >> 3)) * Hsz + (tid & 7) * 8;

    uint4 pf0 = __ldcg((const uint4*)sh0);
    uint4 pf1 = __ldcg((const uint4*)sh1);
    uint4 pf2 = __ldcg((const uint4*)sl0);
    uint4 pf3 = __ldcg((const uint4*)sl1);

    for (int c = 0; c < 8; c++) {
        sts16(Ah + so0, pf0); sts16(Ah + so1, pf1);
        sts16(Al + so0, pf2); sts16(Al + so1, pf3);
        __syncthreads();
        if (c < 7) {
            pf0 = __ldcg((const uint4*)(sh0 + (c + 1) * 64));
            pf1 = __ldcg((const uint4*)(sh1 + (c + 1) * 64));
            pf2 = __ldcg((const uint4*)(sl0 + (c + 1) * 64));
            pf3 = __ldcg((const uint4*)(sl1 + (c + 1) * 64));
        }
        #pragma unroll
        for (int ks = 0; ks < 4; ks++) {
            uint32_t ka = (uint32_t)(ks * 32);
            uint32_t kb = (uint32_t)((c * 64 + ks * 16) * 2);
            uint32_t ah0, ah1, ah2, ah3, al0, al1, al2, al3;
            ldsm4(ah0, ah1, ah2, ah3, Ah + aoff + ka);
            ldsm4(al0, al1, al2, al3, Al + aoff + ka);
            #pragma unroll
            for (int g2 = 0; g2 < NF / 2; g2++) {
                uint32_t bo = boff + (uint32_t)(g2 * 16 * 1040) + kb;
                uint32_t bh0, bh1, bh2, bh3, bl0, bl1, bl2, bl3;
                ldsm4(bh0, bh1, bh2, bh3, sb + wh + bo);
                ldsm4(bl0, bl1, bl2, bl3, sb + wl + bo);
                mma_bf16(d[2*g2],     ah0, ah1, ah2, ah3, bh0, bh1);
                mma_bf16(d[2*g2 + 1], ah0, ah1, ah2, ah3, bh2, bh3);
                mma_bf16(d[2*g2],     ah0, ah1, ah2, ah3, bl0, bl1);
                mma_bf16(d[2*g2 + 1], ah0, ah1, ah2, ah3, bl2, bl3);
                mma_bf16(d[2*g2],     al0, al1, al2, al3, bh0, bh1);
                mma_bf16(d[2*g2 + 1], al0, al1, al2, al3, bh2, bh3);
            }
        }
        __syncthreads();
    }
}

// ---------------- persistent recurrent loop kernel (unchanged from R4) --------
__global__ __launch_bounds__(256, 1) void loop_kernel(float* __restrict__ out) {
    extern __shared__ char smem[];
    uint32_t sb = smem_u32(smem);
    int tid = threadIdx.x, cta = blockIdx.x;
    int wid = tid >> 5, l = tid & 31, g = l >> 2, tg = l & 3;

    int sA  = cta >> 6;
    int tA  = cta & 63;
    int rA0 = (tA >> 3) * 64, jA0 = (tA & 7) * 64;
    int rB0 = (cta >> 4) * 64, jB0 = (cta & 15) * 32;
    const __nv_bfloat16* WAhi = g_W_hi + (size_t)sA * Hsz * Hsz;
    const __nv_bfloat16* WAlo = g_W_lo + (size_t)sA * Hsz * Hsz;
    const __nv_bfloat16* WBhi = g_W_hi + (size_t)2 * Hsz * Hsz;
    const __nv_bfloat16* WBlo = g_W_lo + (size_t)2 * Hsz * Hsz;

    for (int i = tid; i < 4096; i += 256) {
        int r = i >> 6, s = i & 63;
        uint32_t d0 = sb + OFF_WAH + r * 1040 + s * 16;
        cpa16(d0,                       WAhi + (size_t)(jA0 + r) * Hsz + s * 8);
        cpa16(d0 + (OFF_WAL - OFF_WAH), WAlo + (size_t)(jA0 + r) * Hsz + s * 8);
    }
    for (int i = tid; i < 2048; i += 256) {
        int r = i >> 6, s = i & 63;
        uint32_t d0 = sb + OFF_WBH + r * 1040 + s * 16;
        cpa16(d0,                       WBhi + (size_t)(jB0 + r) * Hsz + s * 8);
        cpa16(d0 + (OFF_WBL - OFF_WBH), WBlo + (size_t)(jB0 + r) * Hsz + s * 8);
    }
    asm volatile("cp.async.commit_group;" ::: "memory");
    asm volatile("cp.async.wait_group 0;" ::: "memory");

    __nv_bfloat16 zb = __float2bfloat16(0.f);
    for (int i = tid; i < 2048; i += 256) {
        int o = cta * 2048 + i;
        g_HD[o] = 0.f;
        g_hd_hi[o] = zb;
        g_hd_lo[o] = zb;
    }
    unsigned target = NCTA;
    gsync(target);

    int wr0 = (wid >> 1) * 16;

    for (int t = 0; t < Tsz; t++) {
        {
            float d[4][4];
            run_gemm<4>(sb, OFF_WAH, OFF_WAL, g_hd_hi, g_hd_lo, rA0, tid, d);
            int wn0 = (wid & 1) * 32;
            const float* At = g_A + (size_t)sA * TBH + (size_t)t * BH;
            #pragma unroll
            for (int nf = 0; nf < 4; nf++) {
                int col = jA0 + wn0 + nf * 8 + tg * 2;
                #pragma unroll
                for (int h = 0; h < 2; h++) {
                    int row = rA0 + wr0 + g + h * 8;
                    size_t o = (size_t)row * Hsz + col;
                    float v0 = d[nf][h * 2], v1 = d[nf][h * 2 + 1];
                    float s0 = sigm(v0 + At[o]);
                    float s1 = sigm(v1 + At[o + 1]);
                    if (sA == 0) {
                        float2 zz = {s0, s1};
                        *(float2*)(g_Z + o) = zz;
                    } else {
                        float h0 = __ldcg(g_HD + o), h1 = __ldcg(g_HD + o + 1);
                        float r0v = s0 * h0, r1v = s1 * h1;
                        __nv_bfloat16 hh0 = __float2bfloat16(r0v);
                        __nv_bfloat16 hh1 = __float2bfloat16(r1v);
                        __nv_bfloat162 hp; hp.x = hh0; hp.y = hh1;
                        __nv_bfloat162 lp;
                        lp.x = __float2bfloat16(r0v - __bfloat162float(hh0));
                        lp.y = __float2bfloat16(r1v - __bfloat162float(hh1));
                        *(__nv_bfloat162*)(g_rh_hi + o) = hp;
                        *(__nv_bfloat162*)(g_rh_lo + o) = lp;
                    }
                }
            }
        }
        gsync(target);

        {
            float d[2][4];
            run_gemm<2>(sb, OFF_WBH, OFF_WBL, g_rh_hi, g_rh_lo, rB0, tid, d);
            int wn0 = (wid & 1) * 16;
            const float* An = g_A + (size_t)2 * TBH + (size_t)t * BH;
            const float* ghn = g_gh + (size_t)(t + 1) * BH;
            bool last = (t == Tsz - 1);
            #pragma unroll
            for (int nf = 0; nf < 2; nf++) {
                int col = jB0 + wn0 + nf * 8 + tg * 2;
                #pragma unroll
                for (int h = 0; h < 2; h++) {
                    int row = rB0 + wr0 + g + h * 8;
                    size_t o = (size_t)row * Hsz + col;
                    #pragma unroll
                    for (int q = 0; q < 2; q++) {
                        float ht = tanhf(d[nf][h * 2 + q] + An[o + q]);
                        float z  = __ldcg(g_Z + o + q);
                        float hd = __ldcg(g_HD + o + q);
                        float hp = (1.f - z) * hd + z * ht;
                        if (last) {
                            out[o + q] = hp;
                        } else {
                            float hdn = ghn[o + q] * hp;
                            g_HD[o + q] = hdn;
                            __nv_bfloat16 hh = __float2bfloat16(hdn);
                            g_hd_hi[o + q] = hh;
                            g_hd_lo[o + q] = __float2bfloat16(hdn - __bfloat162float(hh));
                        }
                    }
                }
            }
        }
        gsync(target);
    }
}

// ---------------- launch ----------------
extern "C" void kernel_launch(void* const* d_in, const int* in_sizes, int n_in,
                              void* d_out, int out_size) {
    const float* x    = (const float*)d_in[0];
    const float* xl   = (const float*)d_in[1];
    const float* mk   = (const float*)d_in[2];
    const float* dl   = (const float*)d_in[3];
    const float* xm   = (const float*)d_in[4];
    const float* Wz   = (const float*)d_in[5];
    const float* bz   = (const float*)d_in[6];
    const float* Wr   = (const float*)d_in[7];
    const float* br   = (const float*)d_in[8];
    const float* Wn   = (const float*)d_in[9];
    const float* bn   = (const float*)d_in[10];
    const float* Wgx  = (const float*)d_in[11];
    const float* bgx  = (const float*)d_in[12];
    const float* Wgh  = (const float*)d_in[13];
    const float* bgh  = (const float*)d_in[14];

    static int smem_set = 0;
    if (!smem_set) {
        cudaFuncSetAttribute(loop_kernel,
                             cudaFuncAttributeMaxDynamicSharedMemorySize, SMEM_TOTAL);
        cudaFuncSetAttribute(p1m_kernel,
                             cudaFuncAttributeMaxDynamicSharedMemorySize, PG_SMEM);
        cudaFuncSetAttribute(p2m_kernel,
                             cudaFuncAttributeMaxDynamicSharedMemorySize, PG_SMEM);
        smem_set = 1;
    }

    p0_kernel<<<(TB * Dsz) / 256, 256>>>(x, xl, mk, dl, xm, Wgx, bgx);
    prep_w_kernel<<<(786432 + 393216 + 65536) / 256, 256>>>(Wz, Wr, Wn, Wgh);
    p1m_kernel<<<dim3(TB / 128, Hsz / 128, 3), 256, PG_SMEM>>>(bz, br, bn);
    p2m_kernel<<<dim3(TB / 128, Hsz / 128), 256, PG_SMEM>>>(bgh);
    zero_bar_kernel<<<1, 1>>>();
    loop_kernel<<<NCTA, 256, SMEM_TOTAL>>>((float*)d_out);
}